// round 1
// baseline (speedup 1.0000x reference)
#include <cuda_runtime.h>
#include <math.h>
#include <stdint.h>

// Problem constants
constexpr int kT  = 2048;   // sequence length (B=1)
constexpr int kDm = 1024;   // d_model
constexpr int kDi = 2048;   // d_inner
constexpr int kNL = 4;      // layers
constexpr int kNS = 16;     // SSM state N
constexpr int kKC = 4;      // conv kernel K
constexpr int kV  = 32000;  // vocab
constexpr int kXP = 33;     // 2N+1

// Scratch (no cudaMalloc allowed)
__device__ float g_x [kT * kDm];        // residual stream
__device__ float g_xn[kT * kDm];        // rmsnorm output
__device__ float g_xz[kT * 2 * kDi];    // in_proj output (x_ssm | z)
__device__ float g_u [kT * kDi];        // conv+silu output
__device__ float g_xp[kT * kXP];        // x_proj output (dt | B | C)
__device__ float g_yg[kT * kDi];        // scan output, gated

// ---------------------------------------------------------------------------
// Embedding gather: g_x[t,:] = emb[idx[t],:]
// ---------------------------------------------------------------------------
__global__ void embed_kernel(const int* __restrict__ idx,
                             const float* __restrict__ emb) {
    int t = blockIdx.x;
    int row = idx[t];
    const float4* src = (const float4*)(emb + (size_t)row * kDm);
    float4* dst = (float4*)(g_x + (size_t)t * kDm);
    dst[threadIdx.x] = src[threadIdx.x];   // 256 threads * float4 = 1024 floats
}

// ---------------------------------------------------------------------------
// RMSNorm: one block per row, 256 threads, Dm=1024
// ---------------------------------------------------------------------------
__global__ void rmsnorm_kernel(const float* __restrict__ in,
                               const float* __restrict__ w,
                               float* __restrict__ out) {
    __shared__ float red[8];
    __shared__ float s_scale;
    int t = blockIdx.x;
    float4 v = ((const float4*)(in + (size_t)t * kDm))[threadIdx.x];
    float ss = v.x * v.x + v.y * v.y + v.z * v.z + v.w * v.w;
    #pragma unroll
    for (int o = 16; o; o >>= 1) ss += __shfl_xor_sync(0xffffffffu, ss, o);
    int warp = threadIdx.x >> 5, lane = threadIdx.x & 31;
    if (lane == 0) red[warp] = ss;
    __syncthreads();
    if (threadIdx.x == 0) {
        float s = 0.f;
        #pragma unroll
        for (int i = 0; i < 8; i++) s += red[i];
        s_scale = rsqrtf(s / (float)kDm + 1e-5f);
    }
    __syncthreads();
    float sc = s_scale;
    float4 wv = ((const float4*)w)[threadIdx.x];
    float4 o;
    o.x = v.x * sc * wv.x;
    o.y = v.y * sc * wv.y;
    o.z = v.z * sc * wv.z;
    o.w = v.w * sc * wv.w;
    ((float4*)(out + (size_t)t * kDm))[threadIdx.x] = o;
}

// ---------------------------------------------------------------------------
// Generic NT SGEMM: C[M,N] = A[M,K] @ B[N,K]^T (+ C if accumulate)
// 128x128 block tile, BK=8, 256 threads, 8x8 microtile.
// Requires M%128==0, N%128==0, K%8==0 (true for all call sites).
// ---------------------------------------------------------------------------
__global__ void gemm_nt_kernel(const float* __restrict__ A,
                               const float* __restrict__ B,
                               float* __restrict__ C,
                               int M, int N, int K, int accumulate) {
    __shared__ float As[8][128];
    __shared__ float Bs[8][128];
    int tid = threadIdx.x;
    const float* Ab = A + (size_t)blockIdx.y * 128 * K;
    const float* Bb = B + (size_t)blockIdx.x * 128 * K;
    int lr = tid >> 1;            // 0..127 load row
    int lc = (tid & 1) * 4;       // 0 or 4 load col (float4)
    int tr = (tid >> 4) * 8;      // microtile row base
    int tc = (tid & 15) * 8;      // microtile col base

    float acc[8][8];
    #pragma unroll
    for (int i = 0; i < 8; i++)
        #pragma unroll
        for (int j = 0; j < 8; j++) acc[i][j] = 0.f;

    for (int k0 = 0; k0 < K; k0 += 8) {
        float4 av = *(const float4*)(Ab + (size_t)lr * K + k0 + lc);
        float4 bv = *(const float4*)(Bb + (size_t)lr * K + k0 + lc);
        As[lc + 0][lr] = av.x; As[lc + 1][lr] = av.y;
        As[lc + 2][lr] = av.z; As[lc + 3][lr] = av.w;
        Bs[lc + 0][lr] = bv.x; Bs[lc + 1][lr] = bv.y;
        Bs[lc + 2][lr] = bv.z; Bs[lc + 3][lr] = bv.w;
        __syncthreads();
        #pragma unroll
        for (int k = 0; k < 8; k++) {
            float ar[8], br[8];
            #pragma unroll
            for (int i = 0; i < 8; i++) ar[i] = As[k][tr + i];
            #pragma unroll
            for (int j = 0; j < 8; j++) br[j] = Bs[k][tc + j];
            #pragma unroll
            for (int i = 0; i < 8; i++)
                #pragma unroll
                for (int j = 0; j < 8; j++)
                    acc[i][j] += ar[i] * br[j];
        }
        __syncthreads();
    }

    float* Cb = C + ((size_t)blockIdx.y * 128 + tr) * N + (size_t)blockIdx.x * 128 + tc;
    if (accumulate) {
        #pragma unroll
        for (int i = 0; i < 8; i++)
            #pragma unroll
            for (int j = 0; j < 8; j++)
                Cb[(size_t)i * N + j] += acc[i][j];
    } else {
        #pragma unroll
        for (int i = 0; i < 8; i++)
            #pragma unroll
            for (int j = 0; j < 8; j++)
                Cb[(size_t)i * N + j] = acc[i][j];
    }
}

// ---------------------------------------------------------------------------
// Causal depthwise conv (K=4) over time + bias + silu.
// x_ssm = g_xz[:, 0:Di] (row stride 2*Di). Output g_u[t, c].
// ---------------------------------------------------------------------------
__global__ void conv_silu_kernel(const float* __restrict__ cw,
                                 const float* __restrict__ cb) {
    int i = blockIdx.x * blockDim.x + threadIdx.x;   // t*Di + c
    int t = i / kDi, c = i - t * kDi;
    float w0 = cw[c * 4 + 0], w1 = cw[c * 4 + 1];
    float w2 = cw[c * 4 + 2], w3 = cw[c * 4 + 3];
    const int stride = 2 * kDi;
    float s = cb[c];
    if (t >= 3) s += w0 * g_xz[(size_t)(t - 3) * stride + c];
    if (t >= 2) s += w1 * g_xz[(size_t)(t - 2) * stride + c];
    if (t >= 1) s += w2 * g_xz[(size_t)(t - 1) * stride + c];
    s += w3 * g_xz[(size_t)t * stride + c];
    g_u[i] = s / (1.f + __expf(-s));   // silu
}

// ---------------------------------------------------------------------------
// x_proj: g_xp[t, j] = dot(g_u[t,:], W[j,:]), j in [0, 33). One block per t.
// ---------------------------------------------------------------------------
__global__ void xproj_kernel(const float* __restrict__ W) {
    int t = blockIdx.x;
    int warp = threadIdx.x >> 5, lane = threadIdx.x & 31;
    const float4* ur = (const float4*)(g_u + (size_t)t * kDi);
    for (int j = warp; j < kXP; j += 8) {
        const float4* wr = (const float4*)(W + (size_t)j * kDi);
        float s = 0.f;
        #pragma unroll 4
        for (int k = lane; k < kDi / 4; k += 32) {
            float4 a = ur[k], b = wr[k];
            s += a.x * b.x + a.y * b.y + a.z * b.z + a.w * b.w;
        }
        #pragma unroll
        for (int o = 16; o; o >>= 1) s += __shfl_xor_sync(0xffffffffu, s, o);
        if (lane == 0) g_xp[t * kXP + j] = s;
    }
}

// ---------------------------------------------------------------------------
// Selective scan. 16 lanes = 16 SSM states of one channel d.
// Block = 128 threads = 8 channels; grid = Di/8 = 256 blocks.
// Writes g_yg[t, d] = (y_t[d] + u*Dp) * silu(z[t,d]).
// ---------------------------------------------------------------------------
__global__ void scan_kernel(const float* __restrict__ A_log,
                            const float* __restrict__ dtw_,
                            const float* __restrict__ dtb_,
                            const float* __restrict__ Dp_) {
    int tid = threadIdx.x;
    int n = tid & 15;
    int g = tid >> 4;                    // group in block, 0..7
    int d = blockIdx.x * 8 + g;          // channel
    float a   = -expf(A_log[(size_t)d * kNS + n]);   // A[d,n] (negative)
    float dtw = dtw_[d];
    float dtb = dtb_[d];
    float Dp  = Dp_[d];
    float h = 0.f;
    for (int t = 0; t < kT; t++) {
        const float* xpr = g_xp + (size_t)t * kXP;
        float dtr = xpr[0];
        float xv = dtr * dtw + dtb;
        float dt = (xv > 20.f) ? xv : log1pf(__expf(xv));   // softplus
        float Bn = xpr[1 + n];
        float Cn = xpr[17 + n];
        float ut = g_u[(size_t)t * kDi + d];
        float dA = __expf(dt * a);
        h = dA * h + (dt * ut) * Bn;
        float p = h * Cn;
        p += __shfl_xor_sync(0xffffffffu, p, 8);
        p += __shfl_xor_sync(0xffffffffu, p, 4);
        p += __shfl_xor_sync(0xffffffffu, p, 2);
        p += __shfl_xor_sync(0xffffffffu, p, 1);
        if (n == 0) {
            float z = g_xz[(size_t)t * (2 * kDi) + kDi + d];
            float y = p + ut * Dp;
            g_yg[(size_t)t * kDi + d] = y * (z / (1.f + __expf(-z)));
        }
    }
}

// ---------------------------------------------------------------------------
// Host launcher
// ---------------------------------------------------------------------------
extern "C" void kernel_launch(void* const* d_in, const int* in_sizes, int n_in,
                              void* d_out, int out_size) {
    const int*   idx        = (const int*)  d_in[0];
    const float* emb        = (const float*)d_in[1];
    const float* norm_w     = (const float*)d_in[2];
    const float* in_proj_w  = (const float*)d_in[3];
    const float* conv_w     = (const float*)d_in[4];
    const float* conv_b     = (const float*)d_in[5];
    const float* x_proj_w   = (const float*)d_in[6];
    const float* dt_proj_w  = (const float*)d_in[7];
    const float* dt_proj_b  = (const float*)d_in[8];
    const float* A_log      = (const float*)d_in[9];
    const float* D_param    = (const float*)d_in[10];
    const float* out_proj_w = (const float*)d_in[11];
    const float* norm_f_w   = (const float*)d_in[12];
    float* out = (float*)d_out;

    float *x, *xn, *xz, *yg;
    cudaGetSymbolAddress((void**)&x,  g_x);
    cudaGetSymbolAddress((void**)&xn, g_xn);
    cudaGetSymbolAddress((void**)&xz, g_xz);
    cudaGetSymbolAddress((void**)&yg, g_yg);

    embed_kernel<<<kT, 256>>>(idx, emb);

    for (int l = 0; l < kNL; l++) {
        rmsnorm_kernel<<<kT, 256>>>(x, norm_w + (size_t)l * kDm, xn);
        // xz = xn @ in_proj_w[l]^T : [T, 4096]
        gemm_nt_kernel<<<dim3(2 * kDi / 128, kT / 128), 256>>>(
            xn, in_proj_w + (size_t)l * 2 * kDi * kDm, xz, kT, 2 * kDi, kDm, 0);
        conv_silu_kernel<<<kT * kDi / 256, 256>>>(
            conv_w + (size_t)l * kDi * kKC, conv_b + (size_t)l * kDi);
        xproj_kernel<<<kT, 256>>>(x_proj_w + (size_t)l * kXP * kDi);
        scan_kernel<<<kDi / 8, 128>>>(
            A_log + (size_t)l * kDi * kNS,
            dt_proj_w + (size_t)l * kDi,
            dt_proj_b + (size_t)l * kDi,
            D_param + (size_t)l * kDi);
        // x += yg @ out_proj_w[l]^T : [T, 1024], accumulate (residual)
        gemm_nt_kernel<<<dim3(kDm / 128, kT / 128), 256>>>(
            yg, out_proj_w + (size_t)l * kDm * kDi, x, kT, kDm, kDi, 1);
    }

    rmsnorm_kernel<<<kT, 256>>>(x, norm_f_w, xn);
    // logits = xn @ emb^T : [T, 32000]
    gemm_nt_kernel<<<dim3(kV / 128, kT / 128), 256>>>(xn, emb, out, kT, kV, kDm, 0);
}

// round 2
// speedup vs baseline: 1.4206x; 1.4206x over previous
#include <cuda_runtime.h>
#include <math.h>
#include <stdint.h>

// Problem constants
constexpr int kT  = 2048;   // sequence length (B=1)
constexpr int kDm = 1024;   // d_model
constexpr int kDi = 2048;   // d_inner
constexpr int kNL = 4;      // layers
constexpr int kNS = 16;     // SSM state N
constexpr int kV  = 32000;  // vocab
constexpr int kXP = 33;     // 2N+1

// Scratch (no cudaMalloc allowed)
__device__ float g_x [kT * kDm];        // residual stream
__device__ float g_xn[kT * kDm];        // rmsnorm output
__device__ float g_xz[kT * 2 * kDi];    // in_proj output (x_ssm | z)
__device__ float g_u [kT * kDi];        // conv+silu output
__device__ float g_xp[kT * kXP];        // x_proj output (dt | B | C)
__device__ float g_yg[kT * kDi];        // scan output, gated

// ---------------------------------------------------------------------------
// Embedding gather
// ---------------------------------------------------------------------------
__global__ void embed_kernel(const int* __restrict__ idx,
                             const float* __restrict__ emb) {
    int t = blockIdx.x;
    int row = idx[t];
    const float4* src = (const float4*)(emb + (size_t)row * kDm);
    float4* dst = (float4*)(g_x + (size_t)t * kDm);
    dst[threadIdx.x] = src[threadIdx.x];
}

// ---------------------------------------------------------------------------
// RMSNorm
// ---------------------------------------------------------------------------
__global__ void rmsnorm_kernel(const float* __restrict__ in,
                               const float* __restrict__ w,
                               float* __restrict__ out) {
    __shared__ float red[8];
    __shared__ float s_scale;
    int t = blockIdx.x;
    float4 v = ((const float4*)(in + (size_t)t * kDm))[threadIdx.x];
    float ss = v.x * v.x + v.y * v.y + v.z * v.z + v.w * v.w;
    #pragma unroll
    for (int o = 16; o; o >>= 1) ss += __shfl_xor_sync(0xffffffffu, ss, o);
    int warp = threadIdx.x >> 5, lane = threadIdx.x & 31;
    if (lane == 0) red[warp] = ss;
    __syncthreads();
    if (threadIdx.x == 0) {
        float s = 0.f;
        #pragma unroll
        for (int i = 0; i < 8; i++) s += red[i];
        s_scale = rsqrtf(s / (float)kDm + 1e-5f);
    }
    __syncthreads();
    float sc = s_scale;
    float4 wv = ((const float4*)w)[threadIdx.x];
    float4 o;
    o.x = v.x * sc * wv.x;
    o.y = v.y * sc * wv.y;
    o.z = v.z * sc * wv.z;
    o.w = v.w * sc * wv.w;
    ((float4*)(out + (size_t)t * kDm))[threadIdx.x] = o;
}

// ---------------------------------------------------------------------------
// TF32 tensor-core NT GEMM: C[M,N] = A[M,K] @ B[N,K]^T (+C if accumulate)
// Block tile 128x128, BK=16, 256 threads (8 warps), warp tile 64x32.
// mma.sync.aligned.m16n8k8.row.col.f32.tf32.tf32.f32
// Requires M%128==0, N%128==0, K%16==0.
// ---------------------------------------------------------------------------
#define SMP 136   // smem row pitch (floats): conflict-free fragment loads

__device__ __forceinline__ uint32_t f2tf32(float x) {
    uint32_t r;
    asm("cvt.rna.tf32.f32 %0, %1;" : "=r"(r) : "f"(x));
    return r;
}

__global__ __launch_bounds__(256, 1)
void gemm_tf32_nt(const float* __restrict__ A,
                  const float* __restrict__ B,
                  float* __restrict__ C,
                  int M, int N, int K, int accumulate) {
    __shared__ uint32_t As[2][16][SMP];
    __shared__ uint32_t Bs[2][16][SMP];

    int tid  = threadIdx.x;
    int lane = tid & 31;
    int wrp  = tid >> 5;
    int wm   = wrp >> 2;        // 0..1  -> warp row (64 rows each)
    int wn   = wrp & 3;         // 0..3  -> warp col (32 cols each)

    const float* Ab = A + (size_t)blockIdx.y * 128 * K;
    const float* Bb = B + (size_t)blockIdx.x * 128 * K;

    // Loader mapping: each thread owns one row (tid>>1) and a 32B half (tid&1)
    int lrow = tid >> 1;
    int lk   = (tid & 1) * 8;
    const float* ap = Ab + (size_t)lrow * K + lk;
    const float* bp = Bb + (size_t)lrow * K + lk;

    float4 a0v, a1v, b0v, b1v;
    // prefetch stage 0
    a0v = *(const float4*)(ap + 0);
    a1v = *(const float4*)(ap + 4);
    b0v = *(const float4*)(bp + 0);
    b1v = *(const float4*)(bp + 4);

    float acc[4][4][4];
    #pragma unroll
    for (int i = 0; i < 4; i++)
        #pragma unroll
        for (int j = 0; j < 4; j++)
            #pragma unroll
            for (int r = 0; r < 4; r++) acc[i][j][r] = 0.f;

    int cur = 0;
    // store stage 0
    {
        As[0][lk+0][lrow] = f2tf32(a0v.x); As[0][lk+1][lrow] = f2tf32(a0v.y);
        As[0][lk+2][lrow] = f2tf32(a0v.z); As[0][lk+3][lrow] = f2tf32(a0v.w);
        As[0][lk+4][lrow] = f2tf32(a1v.x); As[0][lk+5][lrow] = f2tf32(a1v.y);
        As[0][lk+6][lrow] = f2tf32(a1v.z); As[0][lk+7][lrow] = f2tf32(a1v.w);
        Bs[0][lk+0][lrow] = f2tf32(b0v.x); Bs[0][lk+1][lrow] = f2tf32(b0v.y);
        Bs[0][lk+2][lrow] = f2tf32(b0v.z); Bs[0][lk+3][lrow] = f2tf32(b0v.w);
        Bs[0][lk+4][lrow] = f2tf32(b1v.x); Bs[0][lk+5][lrow] = f2tf32(b1v.y);
        Bs[0][lk+6][lrow] = f2tf32(b1v.z); Bs[0][lk+7][lrow] = f2tf32(b1v.w);
    }
    __syncthreads();

    int l2 = lane & 3;   // k-phase within frag
    int l4 = lane >> 2;  // row/col within frag

    for (int k0 = 16; k0 <= K; k0 += 16) {
        // prefetch next stage (if any)
        if (k0 < K) {
            a0v = *(const float4*)(ap + k0 + 0);
            a1v = *(const float4*)(ap + k0 + 4);
            b0v = *(const float4*)(bp + k0 + 0);
            b1v = *(const float4*)(bp + k0 + 4);
        }
        // compute current buffer: two k8 steps
        #pragma unroll
        for (int kb = 0; kb < 16; kb += 8) {
            uint32_t af[4][4];
            uint32_t bf[4][2];
            #pragma unroll
            for (int mi = 0; mi < 4; mi++) {
                int m0 = wm * 64 + mi * 16 + l4;
                af[mi][0] = As[cur][kb + l2    ][m0    ];
                af[mi][1] = As[cur][kb + l2    ][m0 + 8];
                af[mi][2] = As[cur][kb + l2 + 4][m0    ];
                af[mi][3] = As[cur][kb + l2 + 4][m0 + 8];
            }
            #pragma unroll
            for (int ni = 0; ni < 4; ni++) {
                int n0 = wn * 32 + ni * 8 + l4;
                bf[ni][0] = Bs[cur][kb + l2    ][n0];
                bf[ni][1] = Bs[cur][kb + l2 + 4][n0];
            }
            #pragma unroll
            for (int mi = 0; mi < 4; mi++)
                #pragma unroll
                for (int ni = 0; ni < 4; ni++) {
                    asm volatile(
                        "mma.sync.aligned.m16n8k8.row.col.f32.tf32.tf32.f32 "
                        "{%0,%1,%2,%3}, {%4,%5,%6,%7}, {%8,%9}, {%0,%1,%2,%3};"
                        : "+f"(acc[mi][ni][0]), "+f"(acc[mi][ni][1]),
                          "+f"(acc[mi][ni][2]), "+f"(acc[mi][ni][3])
                        : "r"(af[mi][0]), "r"(af[mi][1]),
                          "r"(af[mi][2]), "r"(af[mi][3]),
                          "r"(bf[ni][0]), "r"(bf[ni][1]));
                }
        }
        // store next stage
        if (k0 < K) {
            int nxt = cur ^ 1;
            As[nxt][lk+0][lrow] = f2tf32(a0v.x); As[nxt][lk+1][lrow] = f2tf32(a0v.y);
            As[nxt][lk+2][lrow] = f2tf32(a0v.z); As[nxt][lk+3][lrow] = f2tf32(a0v.w);
            As[nxt][lk+4][lrow] = f2tf32(a1v.x); As[nxt][lk+5][lrow] = f2tf32(a1v.y);
            As[nxt][lk+6][lrow] = f2tf32(a1v.z); As[nxt][lk+7][lrow] = f2tf32(a1v.w);
            Bs[nxt][lk+0][lrow] = f2tf32(b0v.x); Bs[nxt][lk+1][lrow] = f2tf32(b0v.y);
            Bs[nxt][lk+2][lrow] = f2tf32(b0v.z); Bs[nxt][lk+3][lrow] = f2tf32(b0v.w);
            Bs[nxt][lk+4][lrow] = f2tf32(b1v.x); Bs[nxt][lk+5][lrow] = f2tf32(b1v.y);
            Bs[nxt][lk+6][lrow] = f2tf32(b1v.z); Bs[nxt][lk+7][lrow] = f2tf32(b1v.w);
            __syncthreads();
            cur = nxt;
        }
    }

    // Epilogue
    #pragma unroll
    for (int mi = 0; mi < 4; mi++) {
        int row0 = blockIdx.y * 128 + wm * 64 + mi * 16 + l4;
        #pragma unroll
        for (int ni = 0; ni < 4; ni++) {
            int col0 = blockIdx.x * 128 + wn * 32 + ni * 8 + 2 * l2;
            float2* p0 = (float2*)(C + (size_t)row0 * N + col0);
            float2* p1 = (float2*)(C + (size_t)(row0 + 8) * N + col0);
            if (accumulate) {
                float2 v0 = *p0, v1 = *p1;
                v0.x += acc[mi][ni][0]; v0.y += acc[mi][ni][1];
                v1.x += acc[mi][ni][2]; v1.y += acc[mi][ni][3];
                *p0 = v0; *p1 = v1;
            } else {
                *p0 = make_float2(acc[mi][ni][0], acc[mi][ni][1]);
                *p1 = make_float2(acc[mi][ni][2], acc[mi][ni][3]);
            }
        }
    }
}

// ---------------------------------------------------------------------------
// Causal depthwise conv (K=4) + bias + silu
// ---------------------------------------------------------------------------
__global__ void conv_silu_kernel(const float* __restrict__ cw,
                                 const float* __restrict__ cb) {
    int i = blockIdx.x * blockDim.x + threadIdx.x;
    int t = i / kDi, c = i - t * kDi;
    float w0 = cw[c * 4 + 0], w1 = cw[c * 4 + 1];
    float w2 = cw[c * 4 + 2], w3 = cw[c * 4 + 3];
    const int stride = 2 * kDi;
    float s = cb[c];
    if (t >= 3) s += w0 * g_xz[(size_t)(t - 3) * stride + c];
    if (t >= 2) s += w1 * g_xz[(size_t)(t - 2) * stride + c];
    if (t >= 1) s += w2 * g_xz[(size_t)(t - 1) * stride + c];
    s += w3 * g_xz[(size_t)t * stride + c];
    g_u[i] = s / (1.f + __expf(-s));   // silu
}

// ---------------------------------------------------------------------------
// x_proj: g_xp[t, j] = dot(g_u[t,:], W[j,:])
// ---------------------------------------------------------------------------
__global__ void xproj_kernel(const float* __restrict__ W) {
    int t = blockIdx.x;
    int warp = threadIdx.x >> 5, lane = threadIdx.x & 31;
    const float4* ur = (const float4*)(g_u + (size_t)t * kDi);
    for (int j = warp; j < kXP; j += 8) {
        const float4* wr = (const float4*)(W + (size_t)j * kDi);
        float s = 0.f;
        #pragma unroll 4
        for (int k = lane; k < kDi / 4; k += 32) {
            float4 a = ur[k], b = wr[k];
            s += a.x * b.x + a.y * b.y + a.z * b.z + a.w * b.w;
        }
        #pragma unroll
        for (int o = 16; o; o >>= 1) s += __shfl_xor_sync(0xffffffffu, s, o);
        if (lane == 0) g_xp[t * kXP + j] = s;
    }
}

// ---------------------------------------------------------------------------
// Selective scan
// ---------------------------------------------------------------------------
__global__ void scan_kernel(const float* __restrict__ A_log,
                            const float* __restrict__ dtw_,
                            const float* __restrict__ dtb_,
                            const float* __restrict__ Dp_) {
    int tid = threadIdx.x;
    int n = tid & 15;
    int g = tid >> 4;
    int d = blockIdx.x * 8 + g;
    float a   = -expf(A_log[(size_t)d * kNS + n]);
    float dtw = dtw_[d];
    float dtb = dtb_[d];
    float Dp  = Dp_[d];
    float h = 0.f;
    for (int t = 0; t < kT; t++) {
        const float* xpr = g_xp + (size_t)t * kXP;
        float dtr = xpr[0];
        float xv = dtr * dtw + dtb;
        float dt = (xv > 20.f) ? xv : log1pf(__expf(xv));
        float Bn = xpr[1 + n];
        float Cn = xpr[17 + n];
        float ut = g_u[(size_t)t * kDi + d];
        float dA = __expf(dt * a);
        h = dA * h + (dt * ut) * Bn;
        float p = h * Cn;
        p += __shfl_xor_sync(0xffffffffu, p, 8);
        p += __shfl_xor_sync(0xffffffffu, p, 4);
        p += __shfl_xor_sync(0xffffffffu, p, 2);
        p += __shfl_xor_sync(0xffffffffu, p, 1);
        if (n == 0) {
            float z = g_xz[(size_t)t * (2 * kDi) + kDi + d];
            float y = p + ut * Dp;
            g_yg[(size_t)t * kDi + d] = y * (z / (1.f + __expf(-z)));
        }
    }
}

// ---------------------------------------------------------------------------
// Host launcher
// ---------------------------------------------------------------------------
extern "C" void kernel_launch(void* const* d_in, const int* in_sizes, int n_in,
                              void* d_out, int out_size) {
    const int*   idx        = (const int*)  d_in[0];
    const float* emb        = (const float*)d_in[1];
    const float* norm_w     = (const float*)d_in[2];
    const float* in_proj_w  = (const float*)d_in[3];
    const float* conv_w     = (const float*)d_in[4];
    const float* conv_b     = (const float*)d_in[5];
    const float* x_proj_w   = (const float*)d_in[6];
    const float* dt_proj_w  = (const float*)d_in[7];
    const float* dt_proj_b  = (const float*)d_in[8];
    const float* A_log      = (const float*)d_in[9];
    const float* D_param    = (const float*)d_in[10];
    const float* out_proj_w = (const float*)d_in[11];
    const float* norm_f_w   = (const float*)d_in[12];
    float* out = (float*)d_out;

    float *x, *xn, *xz, *yg;
    cudaGetSymbolAddress((void**)&x,  g_x);
    cudaGetSymbolAddress((void**)&xn, g_xn);
    cudaGetSymbolAddress((void**)&xz, g_xz);
    cudaGetSymbolAddress((void**)&yg, g_yg);

    embed_kernel<<<kT, 256>>>(idx, emb);

    for (int l = 0; l < kNL; l++) {
        rmsnorm_kernel<<<kT, 256>>>(x, norm_w + (size_t)l * kDm, xn);
        gemm_tf32_nt<<<dim3(2 * kDi / 128, kT / 128), 256>>>(
            xn, in_proj_w + (size_t)l * 2 * kDi * kDm, xz, kT, 2 * kDi, kDm, 0);
        conv_silu_kernel<<<kT * kDi / 256, 256>>>(
            conv_w + (size_t)l * kDi * 4, conv_b + (size_t)l * kDi);
        xproj_kernel<<<kT, 256>>>(x_proj_w + (size_t)l * kXP * kDi);
        scan_kernel<<<kDi / 8, 128>>>(
            A_log + (size_t)l * kDi * kNS,
            dt_proj_w + (size_t)l * kDi,
            dt_proj_b + (size_t)l * kDi,
            D_param + (size_t)l * kDi);
        gemm_tf32_nt<<<dim3(kDm / 128, kT / 128), 256>>>(
            yg, out_proj_w + (size_t)l * kDm * kDi, x, kT, kDm, kDi, 1);
    }

    rmsnorm_kernel<<<kT, 256>>>(x, norm_f_w, xn);
    gemm_tf32_nt<<<dim3(kV / 128, kT / 128), 256>>>(xn, emb, out, kT, kV, kDm, 0);
}

// round 4
// speedup vs baseline: 1.7303x; 1.2180x over previous
#include <cuda_runtime.h>
#include <math.h>
#include <stdint.h>

// Problem constants
constexpr int kT  = 2048;
constexpr int kDm = 1024;
constexpr int kDi = 2048;
constexpr int kNL = 4;
constexpr int kNS = 16;
constexpr int kV  = 32000;
constexpr int kXP = 33;

// Scratch (no cudaMalloc allowed)
__device__ float g_x [kT * kDm];
__device__ float g_xn[kT * kDm];
__device__ float g_xz[kT * 2 * kDi];
__device__ float g_u [kT * kDi];
__device__ float g_xp[kT * kXP];
__device__ float g_yg[kT * kDi];
// tf32-rounded weight copies
__device__ float g_w_in [kNL * 2 * kDi * kDm];
__device__ float g_w_out[kNL * kDm * kDi];
__device__ float g_emb_r[kV * kDm];

// ---------------------------------------------------------------------------
// Helpers
// ---------------------------------------------------------------------------
__device__ __forceinline__ uint32_t smem_u32(const void* p) {
    uint32_t a;
    asm("{ .reg .u64 t; cvta.to.shared.u64 t, %1; cvt.u32.u64 %0, t; }"
        : "=r"(a) : "l"(p));
    return a;
}
__device__ __forceinline__ float f2tf32f(float x) {
    uint32_t r;
    asm("cvt.rna.tf32.f32 %0, %1;" : "=r"(r) : "f"(x));
    return __uint_as_float(r);
}

// ---------------------------------------------------------------------------
// Weight rounding to tf32 (RNA)
// ---------------------------------------------------------------------------
__global__ void round_tf32_kernel(const float* __restrict__ in,
                                  float* __restrict__ out, int n4) {
    int i = blockIdx.x * blockDim.x + threadIdx.x;
    if (i >= n4) return;
    float4 v = ((const float4*)in)[i];
    v.x = f2tf32f(v.x); v.y = f2tf32f(v.y);
    v.z = f2tf32f(v.z); v.w = f2tf32f(v.w);
    ((float4*)out)[i] = v;
}

// ---------------------------------------------------------------------------
// Embedding gather
// ---------------------------------------------------------------------------
__global__ void embed_kernel(const int* __restrict__ idx,
                             const float* __restrict__ emb) {
    int t = blockIdx.x;
    int row = idx[t];
    const float4* src = (const float4*)(emb + (size_t)row * kDm);
    float4* dst = (float4*)(g_x + (size_t)t * kDm);
    dst[threadIdx.x] = src[threadIdx.x];
}

// ---------------------------------------------------------------------------
// RMSNorm, tf32-rounded output
// ---------------------------------------------------------------------------
__global__ void rmsnorm_kernel(const float* __restrict__ in,
                               const float* __restrict__ w,
                               float* __restrict__ out) {
    __shared__ float red[8];
    __shared__ float s_scale;
    int t = blockIdx.x;
    float4 v = ((const float4*)(in + (size_t)t * kDm))[threadIdx.x];
    float ss = v.x * v.x + v.y * v.y + v.z * v.z + v.w * v.w;
    #pragma unroll
    for (int o = 16; o; o >>= 1) ss += __shfl_xor_sync(0xffffffffu, ss, o);
    int warp = threadIdx.x >> 5, lane = threadIdx.x & 31;
    if (lane == 0) red[warp] = ss;
    __syncthreads();
    if (threadIdx.x == 0) {
        float s = 0.f;
        #pragma unroll
        for (int i = 0; i < 8; i++) s += red[i];
        s_scale = rsqrtf(s / (float)kDm + 1e-5f);
    }
    __syncthreads();
    float sc = s_scale;
    float4 wv = ((const float4*)w)[threadIdx.x];
    float4 o;
    o.x = f2tf32f(v.x * sc * wv.x);
    o.y = f2tf32f(v.y * sc * wv.y);
    o.z = f2tf32f(v.z * sc * wv.z);
    o.w = f2tf32f(v.w * sc * wv.w);
    ((float4*)(out + (size_t)t * kDm))[threadIdx.x] = o;
}

// ---------------------------------------------------------------------------
// Pipelined tf32 mma.sync NT GEMM: C[M,N] = A[M,K] @ B[N,K]^T (+C)
// BM=128, BN template (256 or 128), BK=32, 3-stage cp.async, 256 threads.
// Warp grid 2(m) x 4(n); warp tile 64 x BN/4. All inputs pre-rounded to tf32.
// Requires M%128==0, N%BN==0, K%32==0.
// ---------------------------------------------------------------------------
template <int BN>
__global__ __launch_bounds__(256, 1)
void gemm_tc(const float* __restrict__ A, const float* __restrict__ B,
             float* __restrict__ C, int M, int N, int K, int acc_flag) {
    constexpr int BM = 128, BK = 32, S = 3, P = 36;   // P: smem pitch (floats)
    constexpr int ASZ = BM * P;                       // floats / stage
    constexpr int BSZ = BN * P;
    constexpr int WN  = BN / 4;                       // warp n-tile
    constexpr int NI  = WN / 8;                       // n-frags per warp
    extern __shared__ float sm[];

    int tid = threadIdx.x, lane = tid & 31, wrp = tid >> 5;
    int wm = wrp >> 2;            // 0..1
    int wn = wrp & 3;             // 0..3
    int l2 = lane & 3;            // k phase
    int l4 = lane >> 2;           // row/col in frag

    const float* Ab = A + (size_t)blockIdx.y * BM * K;
    const float* Bb = B + (size_t)blockIdx.x * BN * K;
    uint32_t sbase = smem_u32(sm);

    auto load_stage = [&](int j) {
        int buf = j % S;
        uint32_t sA = sbase + (uint32_t)(buf * (ASZ + BSZ)) * 4u;
        uint32_t sB = sA + (uint32_t)ASZ * 4u;
        int k0 = j * BK;
        #pragma unroll
        for (int i = 0; i < BM * 8 / 256; i++) {
            int chunk = tid + i * 256;
            int row = chunk >> 3, c = chunk & 7;
            asm volatile("cp.async.cg.shared.global [%0], [%1], 16;"
                :: "r"(sA + (uint32_t)(row * P + c * 4) * 4u),
                   "l"(Ab + (size_t)row * K + k0 + c * 4));
        }
        #pragma unroll
        for (int i = 0; i < BN * 8 / 256; i++) {
            int chunk = tid + i * 256;
            int row = chunk >> 3, c = chunk & 7;
            asm volatile("cp.async.cg.shared.global [%0], [%1], 16;"
                :: "r"(sB + (uint32_t)(row * P + c * 4) * 4u),
                   "l"(Bb + (size_t)row * K + k0 + c * 4));
        }
        asm volatile("cp.async.commit_group;" ::: "memory");
    };

    float acc[4][NI][4];
    #pragma unroll
    for (int i = 0; i < 4; i++)
        #pragma unroll
        for (int j = 0; j < NI; j++)
            #pragma unroll
            for (int r = 0; r < 4; r++) acc[i][j][r] = 0.f;

    int NK = K / BK;
    load_stage(0);
    load_stage(1);

    for (int ks = 0; ks < NK; ks++) {
        asm volatile("cp.async.wait_group 1;" ::: "memory");
        __syncthreads();
        if (ks + 2 < NK) {
            load_stage(ks + 2);
        } else {
            asm volatile("cp.async.commit_group;" ::: "memory");
        }

        const float* As = sm + (ks % S) * (ASZ + BSZ);
        const float* Bs = As + ASZ;
        #pragma unroll
        for (int kb = 0; kb < BK; kb += 8) {
            uint32_t af[4][4];
            uint32_t bf[NI][2];
            #pragma unroll
            for (int mi = 0; mi < 4; mi++) {
                int m0 = wm * 64 + mi * 16 + l4;
                af[mi][0] = __float_as_uint(As[(m0    ) * P + kb + l2    ]);
                af[mi][1] = __float_as_uint(As[(m0 + 8) * P + kb + l2    ]);
                af[mi][2] = __float_as_uint(As[(m0    ) * P + kb + l2 + 4]);
                af[mi][3] = __float_as_uint(As[(m0 + 8) * P + kb + l2 + 4]);
            }
            #pragma unroll
            for (int ni = 0; ni < NI; ni++) {
                int n0 = wn * WN + ni * 8 + l4;
                bf[ni][0] = __float_as_uint(Bs[n0 * P + kb + l2    ]);
                bf[ni][1] = __float_as_uint(Bs[n0 * P + kb + l2 + 4]);
            }
            #pragma unroll
            for (int mi = 0; mi < 4; mi++)
                #pragma unroll
                for (int ni = 0; ni < NI; ni++) {
                    asm volatile(
                        "mma.sync.aligned.m16n8k8.row.col.f32.tf32.tf32.f32 "
                        "{%0,%1,%2,%3}, {%4,%5,%6,%7}, {%8,%9}, {%0,%1,%2,%3};"
                        : "+f"(acc[mi][ni][0]), "+f"(acc[mi][ni][1]),
                          "+f"(acc[mi][ni][2]), "+f"(acc[mi][ni][3])
                        : "r"(af[mi][0]), "r"(af[mi][1]),
                          "r"(af[mi][2]), "r"(af[mi][3]),
                          "r"(bf[ni][0]), "r"(bf[ni][1]));
                }
        }
        __syncthreads();
    }

    // Epilogue
    #pragma unroll
    for (int mi = 0; mi < 4; mi++) {
        int row0 = blockIdx.y * BM + wm * 64 + mi * 16 + l4;
        #pragma unroll
        for (int ni = 0; ni < NI; ni++) {
            int col0 = blockIdx.x * BN + wn * WN + ni * 8 + 2 * l2;
            float2* p0 = (float2*)(C + (size_t)row0 * N + col0);
            float2* p1 = (float2*)(C + (size_t)(row0 + 8) * N + col0);
            if (acc_flag) {
                float2 v0 = *p0, v1 = *p1;
                v0.x += acc[mi][ni][0]; v0.y += acc[mi][ni][1];
                v1.x += acc[mi][ni][2]; v1.y += acc[mi][ni][3];
                *p0 = v0; *p1 = v1;
            } else {
                *p0 = make_float2(acc[mi][ni][0], acc[mi][ni][1]);
                *p1 = make_float2(acc[mi][ni][2], acc[mi][ni][3]);
            }
        }
    }
}

constexpr int SMEM_BN256 = 3 * (128 + 256) * 36 * 4;   // 165888
constexpr int SMEM_BN128 = 3 * (128 + 128) * 36 * 4;   // 110592

// ---------------------------------------------------------------------------
// Causal depthwise conv (K=4) + bias + silu
// ---------------------------------------------------------------------------
__global__ void conv_silu_kernel(const float* __restrict__ cw,
                                 const float* __restrict__ cb) {
    int i = blockIdx.x * blockDim.x + threadIdx.x;
    int t = i / kDi, c = i - t * kDi;
    float w0 = cw[c * 4 + 0], w1 = cw[c * 4 + 1];
    float w2 = cw[c * 4 + 2], w3 = cw[c * 4 + 3];
    const int stride = 2 * kDi;
    float s = cb[c];
    if (t >= 3) s += w0 * g_xz[(size_t)(t - 3) * stride + c];
    if (t >= 2) s += w1 * g_xz[(size_t)(t - 2) * stride + c];
    if (t >= 1) s += w2 * g_xz[(size_t)(t - 1) * stride + c];
    s += w3 * g_xz[(size_t)t * stride + c];
    g_u[i] = s / (1.f + __expf(-s));
}

// ---------------------------------------------------------------------------
// x_proj
// ---------------------------------------------------------------------------
__global__ void xproj_kernel(const float* __restrict__ W) {
    int t = blockIdx.x;
    int warp = threadIdx.x >> 5, lane = threadIdx.x & 31;
    const float4* ur = (const float4*)(g_u + (size_t)t * kDi);
    for (int j = warp; j < kXP; j += 8) {
        const float4* wr = (const float4*)(W + (size_t)j * kDi);
        float s = 0.f;
        #pragma unroll 4
        for (int k = lane; k < kDi / 4; k += 32) {
            float4 a = ur[k], b = wr[k];
            s += a.x * b.x + a.y * b.y + a.z * b.z + a.w * b.w;
        }
        #pragma unroll
        for (int o = 16; o; o >>= 1) s += __shfl_xor_sync(0xffffffffu, s, o);
        if (lane == 0) g_xp[t * kXP + j] = s;
    }
}

// ---------------------------------------------------------------------------
// Selective scan; tf32-rounded output
// ---------------------------------------------------------------------------
__global__ void scan_kernel(const float* __restrict__ A_log,
                            const float* __restrict__ dtw_,
                            const float* __restrict__ dtb_,
                            const float* __restrict__ Dp_) {
    int tid = threadIdx.x;
    int n = tid & 15;
    int g = tid >> 4;
    int d = blockIdx.x * 8 + g;
    float a   = -expf(A_log[(size_t)d * kNS + n]);
    float dtw = dtw_[d];
    float dtb = dtb_[d];
    float Dp  = Dp_[d];
    float h = 0.f;
    for (int t = 0; t < kT; t++) {
        const float* xpr = g_xp + (size_t)t * kXP;
        float dtr = xpr[0];
        float xv = dtr * dtw + dtb;
        float dt = (xv > 20.f) ? xv : log1pf(__expf(xv));
        float Bn = xpr[1 + n];
        float Cn = xpr[17 + n];
        float ut = g_u[(size_t)t * kDi + d];
        float dA = __expf(dt * a);
        h = dA * h + (dt * ut) * Bn;
        float p = h * Cn;
        p += __shfl_xor_sync(0xffffffffu, p, 8);
        p += __shfl_xor_sync(0xffffffffu, p, 4);
        p += __shfl_xor_sync(0xffffffffu, p, 2);
        p += __shfl_xor_sync(0xffffffffu, p, 1);
        if (n == 0) {
            float z = g_xz[(size_t)t * (2 * kDi) + kDi + d];
            float y = p + ut * Dp;
            g_yg[(size_t)t * kDi + d] = f2tf32f(y * (z / (1.f + __expf(-z))));
        }
    }
}

// ---------------------------------------------------------------------------
// Host launcher
// ---------------------------------------------------------------------------
extern "C" void kernel_launch(void* const* d_in, const int* in_sizes, int n_in,
                              void* d_out, int out_size) {
    const int*   idx        = (const int*)  d_in[0];
    const float* emb        = (const float*)d_in[1];
    const float* norm_w     = (const float*)d_in[2];
    const float* in_proj_w  = (const float*)d_in[3];
    const float* conv_w     = (const float*)d_in[4];
    const float* conv_b     = (const float*)d_in[5];
    const float* x_proj_w   = (const float*)d_in[6];
    const float* dt_proj_w  = (const float*)d_in[7];
    const float* dt_proj_b  = (const float*)d_in[8];
    const float* A_log      = (const float*)d_in[9];
    const float* D_param    = (const float*)d_in[10];
    const float* out_proj_w = (const float*)d_in[11];
    const float* norm_f_w   = (const float*)d_in[12];
    float* out = (float*)d_out;

    float *x, *xn, *xz, *yg, *w_in, *w_out, *emb_r;
    cudaGetSymbolAddress((void**)&x,     g_x);
    cudaGetSymbolAddress((void**)&xn,    g_xn);
    cudaGetSymbolAddress((void**)&xz,    g_xz);
    cudaGetSymbolAddress((void**)&yg,    g_yg);
    cudaGetSymbolAddress((void**)&w_in,  g_w_in);
    cudaGetSymbolAddress((void**)&w_out, g_w_out);
    cudaGetSymbolAddress((void**)&emb_r, g_emb_r);

    cudaFuncSetAttribute(gemm_tc<256>,
                         cudaFuncAttributeMaxDynamicSharedMemorySize, SMEM_BN256);
    cudaFuncSetAttribute(gemm_tc<128>,
                         cudaFuncAttributeMaxDynamicSharedMemorySize, SMEM_BN128);

    // Round weights to tf32 (RNA)
    {
        int n1 = kNL * 2 * kDi * kDm / 4;
        int n2 = kNL * kDm * kDi / 4;
        int n3 = kV * kDm / 4;
        round_tf32_kernel<<<(n1 + 255) / 256, 256>>>(in_proj_w,  w_in,  n1);
        round_tf32_kernel<<<(n2 + 255) / 256, 256>>>(out_proj_w, w_out, n2);
        round_tf32_kernel<<<(n3 + 255) / 256, 256>>>(emb,        emb_r, n3);
    }

    embed_kernel<<<kT, 256>>>(idx, emb);

    for (int l = 0; l < kNL; l++) {
        rmsnorm_kernel<<<kT, 256>>>(x, norm_w + (size_t)l * kDm, xn);
        gemm_tc<256><<<dim3(2 * kDi / 256, kT / 128), 256, SMEM_BN256>>>(
            xn, w_in + (size_t)l * 2 * kDi * kDm, xz, kT, 2 * kDi, kDm, 0);
        conv_silu_kernel<<<kT * kDi / 256, 256>>>(
            conv_w + (size_t)l * kDi * 4, conv_b + (size_t)l * kDi);
        xproj_kernel<<<kT, 256>>>(x_proj_w + (size_t)l * kXP * kDi);
        scan_kernel<<<kDi / 8, 128>>>(
            A_log + (size_t)l * kDi * kNS,
            dt_proj_w + (size_t)l * kDi,
            dt_proj_b + (size_t)l * kDi,
            D_param + (size_t)l * kDi);
        gemm_tc<128><<<dim3(kDm / 128, kT / 128), 256, SMEM_BN128>>>(
            yg, w_out + (size_t)l * kDm * kDi, x, kT, kDm, kDi, 1);
    }

    rmsnorm_kernel<<<kT, 256>>>(x, norm_f_w, xn);
    gemm_tc<256><<<dim3(kV / 256, kT / 128), 256, SMEM_BN256>>>(
        xn, emb_r, out, kT, kV, kDm, 0);
}

// round 5
// speedup vs baseline: 1.9794x; 1.1439x over previous
#include <cuda_runtime.h>
#include <cuda_fp16.h>
#include <math.h>
#include <stdint.h>

// Problem constants
constexpr int kT  = 2048;
constexpr int kDm = 1024;
constexpr int kDi = 2048;
constexpr int kNL = 4;
constexpr int kNS = 16;
constexpr int kV  = 32000;
constexpr int kXP = 33;

// Scratch (no cudaMalloc allowed)
__device__ float  g_x  [kT * kDm];          // residual (fp32)
__device__ __half g_xnh[kT * kDm];          // rmsnorm out (fp16, GEMM A)
__device__ float  g_xz [kT * 2 * kDi];      // in_proj out (x_ssm | z)
__device__ float  g_u  [kT * kDi];          // conv+silu out
__device__ float  g_xp [kT * kXP];          // x_proj out
__device__ __half g_ygh[kT * kDi];          // scan out gated (fp16, GEMM A)
// fp16 weight copies
__device__ __half g_wh_in [kNL * 2 * kDi * kDm];
__device__ __half g_wh_out[kNL * kDm * kDi];
__device__ __half g_embh  [kV * kDm];

// ---------------------------------------------------------------------------
__device__ __forceinline__ uint32_t smem_u32(const void* p) {
    uint32_t a;
    asm("{ .reg .u64 t; cvta.to.shared.u64 t, %1; cvt.u32.u64 %0, t; }"
        : "=r"(a) : "l"(p));
    return a;
}

// f32 -> f16 conversion (RNE)
__global__ void f32_to_f16_kernel(const float* __restrict__ in,
                                  __half2* __restrict__ out, int n4) {
    int i = blockIdx.x * blockDim.x + threadIdx.x;
    if (i >= n4) return;
    float4 v = ((const float4*)in)[i];
    out[2 * i + 0] = __floats2half2_rn(v.x, v.y);
    out[2 * i + 1] = __floats2half2_rn(v.z, v.w);
}

// ---------------------------------------------------------------------------
// Embedding gather (fp32 residual)
// ---------------------------------------------------------------------------
__global__ void embed_kernel(const int* __restrict__ idx,
                             const float* __restrict__ emb) {
    int t = blockIdx.x;
    int row = idx[t];
    const float4* src = (const float4*)(emb + (size_t)row * kDm);
    float4* dst = (float4*)(g_x + (size_t)t * kDm);
    dst[threadIdx.x] = src[threadIdx.x];
}

// ---------------------------------------------------------------------------
// RMSNorm -> fp16 output
// ---------------------------------------------------------------------------
__global__ void rmsnorm_kernel(const float* __restrict__ in,
                               const float* __restrict__ w,
                               __half* __restrict__ out) {
    __shared__ float red[8];
    __shared__ float s_scale;
    int t = blockIdx.x;
    float4 v = ((const float4*)(in + (size_t)t * kDm))[threadIdx.x];
    float ss = v.x * v.x + v.y * v.y + v.z * v.z + v.w * v.w;
    #pragma unroll
    for (int o = 16; o; o >>= 1) ss += __shfl_xor_sync(0xffffffffu, ss, o);
    int warp = threadIdx.x >> 5, lane = threadIdx.x & 31;
    if (lane == 0) red[warp] = ss;
    __syncthreads();
    if (threadIdx.x == 0) {
        float s = 0.f;
        #pragma unroll
        for (int i = 0; i < 8; i++) s += red[i];
        s_scale = rsqrtf(s / (float)kDm + 1e-5f);
    }
    __syncthreads();
    float sc = s_scale;
    float4 wv = ((const float4*)w)[threadIdx.x];
    __half2 h0 = __floats2half2_rn(v.x * sc * wv.x, v.y * sc * wv.y);
    __half2 h1 = __floats2half2_rn(v.z * sc * wv.z, v.w * sc * wv.w);
    __half2* o = (__half2*)(out + (size_t)t * kDm);
    o[2 * threadIdx.x + 0] = h0;
    o[2 * threadIdx.x + 1] = h1;
}

// ---------------------------------------------------------------------------
// Pipelined fp16 mma.sync NT GEMM: C[M,N](fp32) = A[M,K] @ B[N,K]^T (+C)
// BM=128, BN in {256,128}, BK=32, 3-stage cp.async, 256 threads.
// Warp grid 2(m) x 4(n); warp tile 64 x BN/4. m16n8k16.f16, fp32 accum.
// Smem pitch P=40 halves: conflict-free fragment LDS.
// ---------------------------------------------------------------------------
template <int BN>
__global__ __launch_bounds__(256, 1)
void gemm_hf(const __half* __restrict__ A, const __half* __restrict__ B,
             float* __restrict__ C, int M, int N, int K, int acc_flag) {
    constexpr int BM = 128, BK = 32, S = 3, P = 40;   // P in halves
    constexpr int ASZ = BM * P;                       // halves / stage
    constexpr int BSZ = BN * P;
    constexpr int WN  = BN / 4;
    constexpr int NI  = WN / 8;
    extern __shared__ __half sm[];

    int tid = threadIdx.x, lane = tid & 31, wrp = tid >> 5;
    int wm = wrp >> 2;
    int wn = wrp & 3;
    int l2 = lane & 3;
    int l4 = lane >> 2;

    const __half* Ab = A + (size_t)blockIdx.y * BM * K;
    const __half* Bb = B + (size_t)blockIdx.x * BN * K;
    uint32_t sbase = smem_u32(sm);

    auto load_stage = [&](int j) {
        int buf = j % S;
        uint32_t sA = sbase + (uint32_t)(buf * (ASZ + BSZ)) * 2u;
        uint32_t sB = sA + (uint32_t)ASZ * 2u;
        int k0 = j * BK;
        #pragma unroll
        for (int i = 0; i < BM * 4 / 256; i++) {     // 16B chunks: 4/row
            int chunk = tid + i * 256;
            int row = chunk >> 2, c = chunk & 3;
            asm volatile("cp.async.cg.shared.global [%0], [%1], 16;"
                :: "r"(sA + (uint32_t)(row * P + c * 8) * 2u),
                   "l"(Ab + (size_t)row * K + k0 + c * 8));
        }
        #pragma unroll
        for (int i = 0; i < BN * 4 / 256; i++) {
            int chunk = tid + i * 256;
            int row = chunk >> 2, c = chunk & 3;
            asm volatile("cp.async.cg.shared.global [%0], [%1], 16;"
                :: "r"(sB + (uint32_t)(row * P + c * 8) * 2u),
                   "l"(Bb + (size_t)row * K + k0 + c * 8));
        }
        asm volatile("cp.async.commit_group;" ::: "memory");
    };

    float acc[4][NI][4];
    #pragma unroll
    for (int i = 0; i < 4; i++)
        #pragma unroll
        for (int j = 0; j < NI; j++)
            #pragma unroll
            for (int r = 0; r < 4; r++) acc[i][j][r] = 0.f;

    int NK = K / BK;
    load_stage(0);
    load_stage(1);

    for (int ks = 0; ks < NK; ks++) {
        asm volatile("cp.async.wait_group 1;" ::: "memory");
        __syncthreads();
        if (ks + 2 < NK) {
            load_stage(ks + 2);
        } else {
            asm volatile("cp.async.commit_group;" ::: "memory");
        }

        const __half* As = sm + (ks % S) * (ASZ + BSZ);
        const __half* Bs = As + ASZ;
        #pragma unroll
        for (int kb = 0; kb < BK; kb += 16) {        // 2 k16 phases
            uint32_t af[4][4];
            uint32_t bf[NI][2];
            #pragma unroll
            for (int mi = 0; mi < 4; mi++) {
                int m0 = wm * 64 + mi * 16 + l4;
                af[mi][0] = *(const uint32_t*)(As + (m0    ) * P + kb     + l2 * 2);
                af[mi][1] = *(const uint32_t*)(As + (m0 + 8) * P + kb     + l2 * 2);
                af[mi][2] = *(const uint32_t*)(As + (m0    ) * P + kb + 8 + l2 * 2);
                af[mi][3] = *(const uint32_t*)(As + (m0 + 8) * P + kb + 8 + l2 * 2);
            }
            #pragma unroll
            for (int ni = 0; ni < NI; ni++) {
                int n0 = wn * WN + ni * 8 + l4;
                bf[ni][0] = *(const uint32_t*)(Bs + n0 * P + kb     + l2 * 2);
                bf[ni][1] = *(const uint32_t*)(Bs + n0 * P + kb + 8 + l2 * 2);
            }
            #pragma unroll
            for (int mi = 0; mi < 4; mi++)
                #pragma unroll
                for (int ni = 0; ni < NI; ni++) {
                    asm volatile(
                        "mma.sync.aligned.m16n8k16.row.col.f32.f16.f16.f32 "
                        "{%0,%1,%2,%3}, {%4,%5,%6,%7}, {%8,%9}, {%0,%1,%2,%3};"
                        : "+f"(acc[mi][ni][0]), "+f"(acc[mi][ni][1]),
                          "+f"(acc[mi][ni][2]), "+f"(acc[mi][ni][3])
                        : "r"(af[mi][0]), "r"(af[mi][1]),
                          "r"(af[mi][2]), "r"(af[mi][3]),
                          "r"(bf[ni][0]), "r"(bf[ni][1]));
                }
        }
        __syncthreads();
    }

    // Epilogue
    #pragma unroll
    for (int mi = 0; mi < 4; mi++) {
        int row0 = blockIdx.y * BM + wm * 64 + mi * 16 + l4;
        #pragma unroll
        for (int ni = 0; ni < NI; ni++) {
            int col0 = blockIdx.x * BN + wn * WN + ni * 8 + 2 * l2;
            float2* p0 = (float2*)(C + (size_t)row0 * N + col0);
            float2* p1 = (float2*)(C + (size_t)(row0 + 8) * N + col0);
            if (acc_flag) {
                float2 v0 = *p0, v1 = *p1;
                v0.x += acc[mi][ni][0]; v0.y += acc[mi][ni][1];
                v1.x += acc[mi][ni][2]; v1.y += acc[mi][ni][3];
                *p0 = v0; *p1 = v1;
            } else {
                *p0 = make_float2(acc[mi][ni][0], acc[mi][ni][1]);
                *p1 = make_float2(acc[mi][ni][2], acc[mi][ni][3]);
            }
        }
    }
}

constexpr int SMEM_BN256 = 3 * (128 + 256) * 40 * 2;   // 92160
constexpr int SMEM_BN128 = 3 * (128 + 128) * 40 * 2;   // 61440

// ---------------------------------------------------------------------------
// Causal depthwise conv (K=4) + bias + silu
// ---------------------------------------------------------------------------
__global__ void conv_silu_kernel(const float* __restrict__ cw,
                                 const float* __restrict__ cb) {
    int i = blockIdx.x * blockDim.x + threadIdx.x;
    int t = i / kDi, c = i - t * kDi;
    float w0 = cw[c * 4 + 0], w1 = cw[c * 4 + 1];
    float w2 = cw[c * 4 + 2], w3 = cw[c * 4 + 3];
    const int stride = 2 * kDi;
    float s = cb[c];
    if (t >= 3) s += w0 * g_xz[(size_t)(t - 3) * stride + c];
    if (t >= 2) s += w1 * g_xz[(size_t)(t - 2) * stride + c];
    if (t >= 1) s += w2 * g_xz[(size_t)(t - 1) * stride + c];
    s += w3 * g_xz[(size_t)t * stride + c];
    g_u[i] = s / (1.f + __expf(-s));
}

// ---------------------------------------------------------------------------
// x_proj
// ---------------------------------------------------------------------------
__global__ void xproj_kernel(const float* __restrict__ W) {
    int t = blockIdx.x;
    int warp = threadIdx.x >> 5, lane = threadIdx.x & 31;
    const float4* ur = (const float4*)(g_u + (size_t)t * kDi);
    for (int j = warp; j < kXP; j += 8) {
        const float4* wr = (const float4*)(W + (size_t)j * kDi);
        float s = 0.f;
        #pragma unroll 4
        for (int k = lane; k < kDi / 4; k += 32) {
            float4 a = ur[k], b = wr[k];
            s += a.x * b.x + a.y * b.y + a.z * b.z + a.w * b.w;
        }
        #pragma unroll
        for (int o = 16; o; o >>= 1) s += __shfl_xor_sync(0xffffffffu, s, o);
        if (lane == 0) g_xp[t * kXP + j] = s;
    }
}

// ---------------------------------------------------------------------------
// Selective scan -> fp16 gated output
// ---------------------------------------------------------------------------
__global__ void scan_kernel(const float* __restrict__ A_log,
                            const float* __restrict__ dtw_,
                            const float* __restrict__ dtb_,
                            const float* __restrict__ Dp_) {
    int tid = threadIdx.x;
    int n = tid & 15;
    int g = tid >> 4;
    int d = blockIdx.x * 8 + g;
    float a   = -expf(A_log[(size_t)d * kNS + n]);
    float dtw = dtw_[d];
    float dtb = dtb_[d];
    float Dp  = Dp_[d];
    float h = 0.f;
    for (int t = 0; t < kT; t++) {
        const float* xpr = g_xp + (size_t)t * kXP;
        float dtr = xpr[0];
        float xv = dtr * dtw + dtb;
        float dt = (xv > 20.f) ? xv : log1pf(__expf(xv));
        float Bn = xpr[1 + n];
        float Cn = xpr[17 + n];
        float ut = g_u[(size_t)t * kDi + d];
        float dA = __expf(dt * a);
        h = dA * h + (dt * ut) * Bn;
        float p = h * Cn;
        p += __shfl_xor_sync(0xffffffffu, p, 8);
        p += __shfl_xor_sync(0xffffffffu, p, 4);
        p += __shfl_xor_sync(0xffffffffu, p, 2);
        p += __shfl_xor_sync(0xffffffffu, p, 1);
        if (n == 0) {
            float z = g_xz[(size_t)t * (2 * kDi) + kDi + d];
            float y = p + ut * Dp;
            g_ygh[(size_t)t * kDi + d] = __float2half_rn(y * (z / (1.f + __expf(-z))));
        }
    }
}

// ---------------------------------------------------------------------------
// Host launcher
// ---------------------------------------------------------------------------
extern "C" void kernel_launch(void* const* d_in, const int* in_sizes, int n_in,
                              void* d_out, int out_size) {
    const int*   idx        = (const int*)  d_in[0];
    const float* emb        = (const float*)d_in[1];
    const float* norm_w     = (const float*)d_in[2];
    const float* in_proj_w  = (const float*)d_in[3];
    const float* conv_w     = (const float*)d_in[4];
    const float* conv_b     = (const float*)d_in[5];
    const float* x_proj_w   = (const float*)d_in[6];
    const float* dt_proj_w  = (const float*)d_in[7];
    const float* dt_proj_b  = (const float*)d_in[8];
    const float* A_log      = (const float*)d_in[9];
    const float* D_param    = (const float*)d_in[10];
    const float* out_proj_w = (const float*)d_in[11];
    const float* norm_f_w   = (const float*)d_in[12];
    float* out = (float*)d_out;

    float *x, *xz;
    __half *xnh, *ygh, *wh_in, *wh_out, *embh;
    cudaGetSymbolAddress((void**)&x,      g_x);
    cudaGetSymbolAddress((void**)&xnh,    g_xnh);
    cudaGetSymbolAddress((void**)&xz,     g_xz);
    cudaGetSymbolAddress((void**)&ygh,    g_ygh);
    cudaGetSymbolAddress((void**)&wh_in,  g_wh_in);
    cudaGetSymbolAddress((void**)&wh_out, g_wh_out);
    cudaGetSymbolAddress((void**)&embh,   g_embh);

    cudaFuncSetAttribute(gemm_hf<256>,
                         cudaFuncAttributeMaxDynamicSharedMemorySize, SMEM_BN256);
    cudaFuncSetAttribute(gemm_hf<128>,
                         cudaFuncAttributeMaxDynamicSharedMemorySize, SMEM_BN128);

    // Convert weights to fp16 (RNE)
    {
        int n1 = kNL * 2 * kDi * kDm / 4;
        int n2 = kNL * kDm * kDi / 4;
        int n3 = kV * kDm / 4;
        f32_to_f16_kernel<<<(n1 + 255) / 256, 256>>>(in_proj_w,  (__half2*)wh_in,  n1);
        f32_to_f16_kernel<<<(n2 + 255) / 256, 256>>>(out_proj_w, (__half2*)wh_out, n2);
        f32_to_f16_kernel<<<(n3 + 255) / 256, 256>>>(emb,        (__half2*)embh,   n3);
    }

    embed_kernel<<<kT, 256>>>(idx, emb);

    for (int l = 0; l < kNL; l++) {
        rmsnorm_kernel<<<kT, 256>>>(x, norm_w + (size_t)l * kDm, xnh);
        gemm_hf<256><<<dim3(2 * kDi / 256, kT / 128), 256, SMEM_BN256>>>(
            xnh, wh_in + (size_t)l * 2 * kDi * kDm, xz, kT, 2 * kDi, kDm, 0);
        conv_silu_kernel<<<kT * kDi / 256, 256>>>(
            conv_w + (size_t)l * kDi * 4, conv_b + (size_t)l * kDi);
        xproj_kernel<<<kT, 256>>>(x_proj_w + (size_t)l * kXP * kDi);
        scan_kernel<<<kDi / 8, 128>>>(
            A_log + (size_t)l * kDi * kNS,
            dt_proj_w + (size_t)l * kDi,
            dt_proj_b + (size_t)l * kDi,
            D_param + (size_t)l * kDi);
        gemm_hf<128><<<dim3(kDm / 128, kT / 128), 256, SMEM_BN128>>>(
            ygh, wh_out + (size_t)l * kDm * kDi, x, kT, kDm, kDi, 1);
    }

    rmsnorm_kernel<<<kT, 256>>>(x, norm_f_w, xnh);
    gemm_hf<256><<<dim3(kV / 256, kT / 128), 256, SMEM_BN256>>>(
        xnh, embh, out, kT, kV, kDm, 0);
}

// round 6
// speedup vs baseline: 1.9942x; 1.0075x over previous
#include <cuda_runtime.h>
#include <cuda_fp16.h>
#include <math.h>
#include <stdint.h>

// Problem constants
constexpr int kT  = 2048;
constexpr int kDm = 1024;
constexpr int kDi = 2048;
constexpr int kNL = 4;
constexpr int kNS = 16;
constexpr int kV  = 32000;
constexpr int kXP = 33;

// Scratch (no cudaMalloc allowed). Packed fp16 buffers are tile-major:
// tile = 128 rows x 32 halves (8KB), XOR-swizzled (bits [5:3] ^= row&7).
__device__ float  g_x  [kT * kDm];                     // residual (fp32)
__device__ __align__(16) __half g_xnh[kT * kDm];       // rmsnorm out, packed
__device__ float  g_xz [kT * 2 * kDi];                 // in_proj out
__device__ float  g_u  [kT * kDi];                     // conv+silu out
__device__ float  g_xp [kT * kXP];                     // x_proj out
__device__ __align__(16) __half g_ygh[kT * kDi];       // scan out, packed
__device__ __align__(16) __half g_wh_in [kNL * 2 * kDi * kDm]; // packed 256-row tiles
__device__ __align__(16) __half g_wh_out[kNL * kDm * kDi];     // packed 128-row tiles
__device__ __align__(16) __half g_embh  [kV * kDm];            // packed 256-row tiles

// ---------------------------------------------------------------------------
__device__ __forceinline__ uint32_t smem_u32(const void* p) {
    uint32_t a;
    asm("{ .reg .u64 t; cvta.to.shared.u64 t, %1; cvt.u32.u64 %0, t; }"
        : "=r"(a) : "l"(p));
    return a;
}

#define MBAR_INIT(a, n) \
    asm volatile("mbarrier.init.shared.b64 [%0], %1;" :: "r"(a), "r"(n) : "memory")
#define MBAR_EXPECT_TX(a, tx) \
    asm volatile("mbarrier.arrive.expect_tx.shared.b64 _, [%0], %1;" \
                 :: "r"(a), "r"(tx) : "memory")
#define MBAR_WAIT(a, ph) do {                                                \
    asm volatile(                                                            \
        "{\n\t.reg .pred P;\n"                                               \
        "W%=:\n\t"                                                           \
        "mbarrier.try_wait.parity.acquire.cta.shared::cta.b64 P, [%0], %1, 0x989680;\n\t" \
        "@P bra.uni D%=;\n\t"                                                \
        "bra.uni W%=;\n"                                                     \
        "D%=:\n\t}"                                                          \
        :: "r"(a), "r"(ph) : "memory");                                      \
} while (0)
#define BULK_LD(dst, src, bytes, bar) \
    asm volatile("cp.async.bulk.shared::cluster.global.mbarrier::complete_tx::bytes " \
                 "[%0], [%1], %2, [%3];" \
                 :: "r"(dst), "l"(src), "r"(bytes), "r"(bar) : "memory")

// ---------------------------------------------------------------------------
// Weight pack: f32 [N,K] row-major -> fp16 tiles [nb][kb][R x 32], swizzled.
// ---------------------------------------------------------------------------
template <int R>
__global__ void pack_w_kernel(const float* __restrict__ in,
                              __half* __restrict__ out, int N, int K) {
    long i = (long)blockIdx.x * blockDim.x + threadIdx.x;
    long e = i * 4;
    if (e >= (long)N * K) return;
    int n = (int)(e / K), k = (int)(e % K);
    float4 v = *(const float4*)(in + e);
    int nb = n / R, rr = n % R, kb = k >> 5, col = k & 31;
    int NKt = K >> 5;
    size_t off = ((size_t)(nb * NKt + kb) * (R * 64)) +
                 (uint32_t)((rr * 64 + col * 2) ^ ((rr & 7) << 3));
    __half2 h0 = __floats2half2_rn(v.x, v.y);
    __half2 h1 = __floats2half2_rn(v.z, v.w);
    uint2 u;
    u.x = *(uint32_t*)&h0; u.y = *(uint32_t*)&h1;
    *(uint2*)((char*)out + off) = u;
}

// ---------------------------------------------------------------------------
// Embedding gather (fp32 residual)
// ---------------------------------------------------------------------------
__global__ void embed_kernel(const int* __restrict__ idx,
                             const float* __restrict__ emb) {
    int t = blockIdx.x;
    int row = idx[t];
    const float4* src = (const float4*)(emb + (size_t)row * kDm);
    float4* dst = (float4*)(g_x + (size_t)t * kDm);
    dst[threadIdx.x] = src[threadIdx.x];
}

// ---------------------------------------------------------------------------
// RMSNorm -> packed swizzled fp16 (tile rows 128, K=kDm)
// ---------------------------------------------------------------------------
__global__ void rmsnorm_kernel(const float* __restrict__ in,
                               const float* __restrict__ w,
                               __half* __restrict__ out) {
    __shared__ float red[8];
    __shared__ float s_scale;
    int t = blockIdx.x;
    float4 v = ((const float4*)(in + (size_t)t * kDm))[threadIdx.x];
    float ss = v.x * v.x + v.y * v.y + v.z * v.z + v.w * v.w;
    #pragma unroll
    for (int o = 16; o; o >>= 1) ss += __shfl_xor_sync(0xffffffffu, ss, o);
    int warp = threadIdx.x >> 5, lane = threadIdx.x & 31;
    if (lane == 0) red[warp] = ss;
    __syncthreads();
    if (threadIdx.x == 0) {
        float s = 0.f;
        #pragma unroll
        for (int i = 0; i < 8; i++) s += red[i];
        s_scale = rsqrtf(s / (float)kDm + 1e-5f);
    }
    __syncthreads();
    float sc = s_scale;
    float4 wv = ((const float4*)w)[threadIdx.x];
    __half2 h0 = __floats2half2_rn(v.x * sc * wv.x, v.y * sc * wv.y);
    __half2 h1 = __floats2half2_rn(v.z * sc * wv.z, v.w * sc * wv.w);
    // packed address: d0 = 4*tid
    int d0 = threadIdx.x * 4;
    int tb = t >> 7, r = t & 127, kb = d0 >> 5, col = d0 & 31;
    const int NKt = kDm >> 5;   // 32
    size_t off = ((size_t)(tb * NKt + kb) * 8192) +
                 (uint32_t)((r * 64 + col * 2) ^ ((r & 7) << 3));
    uint2 u;
    u.x = *(uint32_t*)&h0; u.y = *(uint32_t*)&h1;
    *(uint2*)((char*)out + off) = u;
}

// ---------------------------------------------------------------------------
// fp16 mma.sync NT GEMM with cp.async.bulk pipeline.
// A packed 128-row tiles; B packed BN-row tiles (both 32-half k-chunks,
// swizzled). C fp32 row-major [M, N] (+= if acc_flag).
// BM=128, BN in {256,128}; THREADS = 2 * (BN/32) warps * 32.
// Warp grid 2(m) x BN/32(n); warp tile 64x32; m16n8k16.f16 fp32-accum.
// ---------------------------------------------------------------------------
template <int BN, int THREADS>
__global__ __launch_bounds__(THREADS, (BN == 128) ? 2 : 1)
void gemm_bulk(const __half* __restrict__ Ap, const __half* __restrict__ Bp,
               float* __restrict__ C, int M, int N, int K, int acc_flag) {
    constexpr int S  = 3;
    constexpr int SB = 8192 + BN * 64;        // stage bytes (A tile + B tile)
    constexpr int WNN = BN / 32;              // warps along n
    extern __shared__ char sm[];
    uint32_t sb = smem_u32(sm);               // [0..64): mbarriers; bufs at 1024

    int tid = threadIdx.x, lane = tid & 31, wrp = tid >> 5;
    int wm = wrp / WNN, wn = wrp % WNN;
    int l2 = lane & 3, l4 = lane >> 2;
    int NKt = K >> 5;

    const char* gA = (const char*)Ap + (size_t)blockIdx.y * NKt * 8192;
    const char* gB = (const char*)Bp + (size_t)blockIdx.x * NKt * (BN * 64);

    if (tid == 0) {
        #pragma unroll
        for (int s = 0; s < S; s++) MBAR_INIT(sb + 8 * s, 1);
    }
    __syncthreads();

    auto issue = [&](int j) {
        uint32_t bar = sb + 8 * (j % S);
        uint32_t dA  = sb + 1024 + (j % S) * SB;
        MBAR_EXPECT_TX(bar, (uint32_t)SB);
        BULK_LD(dA, gA + (size_t)j * 8192, 8192u, bar);
        BULK_LD(dA + 8192, gB + (size_t)j * (BN * 64), (uint32_t)(BN * 64), bar);
    };
    if (tid == 0) { issue(0); issue(1); }

    float acc[4][4][4];
    #pragma unroll
    for (int i = 0; i < 4; i++)
        #pragma unroll
        for (int j = 0; j < 4; j++)
            #pragma unroll
            for (int r = 0; r < 4; r++) acc[i][j][r] = 0.f;

    // Pre-swizzled column byte offsets for the 4 k-sub-chunks (8 halves each)
    uint32_t cx[4];
    #pragma unroll
    for (int p = 0; p < 4; p++) cx[p] = (uint32_t)((p * 16 + 4 * l2) ^ (l4 << 3));

    for (int ks = 0; ks < NKt; ks++) {
        MBAR_WAIT(sb + 8 * (ks % S), (ks / S) & 1);

        const char* As = sm + 1024 + (ks % S) * SB;
        const char* Bs = As + 8192;
        #pragma unroll
        for (int ph = 0; ph < 2; ph++) {       // k16 phases
            uint32_t af[4][4];
            uint32_t bf[4][2];
            #pragma unroll
            for (int mi = 0; mi < 4; mi++) {
                uint32_t rb = (uint32_t)(wm * 64 + mi * 16 + l4) * 64;
                af[mi][0] = *(const uint32_t*)(As + rb       + cx[ph * 2]);
                af[mi][1] = *(const uint32_t*)(As + rb + 512 + cx[ph * 2]);
                af[mi][2] = *(const uint32_t*)(As + rb       + cx[ph * 2 + 1]);
                af[mi][3] = *(const uint32_t*)(As + rb + 512 + cx[ph * 2 + 1]);
            }
            #pragma unroll
            for (int ni = 0; ni < 4; ni++) {
                uint32_t rb = (uint32_t)(wn * 32 + ni * 8 + l4) * 64;
                bf[ni][0] = *(const uint32_t*)(Bs + rb + cx[ph * 2]);
                bf[ni][1] = *(const uint32_t*)(Bs + rb + cx[ph * 2 + 1]);
            }
            #pragma unroll
            for (int mi = 0; mi < 4; mi++)
                #pragma unroll
                for (int ni = 0; ni < 4; ni++) {
                    asm volatile(
                        "mma.sync.aligned.m16n8k16.row.col.f32.f16.f16.f32 "
                        "{%0,%1,%2,%3}, {%4,%5,%6,%7}, {%8,%9}, {%0,%1,%2,%3};"
                        : "+f"(acc[mi][ni][0]), "+f"(acc[mi][ni][1]),
                          "+f"(acc[mi][ni][2]), "+f"(acc[mi][ni][3])
                        : "r"(af[mi][0]), "r"(af[mi][1]),
                          "r"(af[mi][2]), "r"(af[mi][3]),
                          "r"(bf[ni][0]), "r"(bf[ni][1]));
                }
        }
        __syncthreads();
        if (tid == 0 && ks + 2 < NKt) issue(ks + 2);
    }

    // Epilogue
    #pragma unroll
    for (int mi = 0; mi < 4; mi++) {
        int row0 = blockIdx.y * 128 + wm * 64 + mi * 16 + l4;
        #pragma unroll
        for (int ni = 0; ni < 4; ni++) {
            int col0 = blockIdx.x * BN + wn * 32 + ni * 8 + 2 * l2;
            float2* p0 = (float2*)(C + (size_t)row0 * N + col0);
            float2* p1 = (float2*)(C + (size_t)(row0 + 8) * N + col0);
            if (acc_flag) {
                float2 v0 = *p0, v1 = *p1;
                v0.x += acc[mi][ni][0]; v0.y += acc[mi][ni][1];
                v1.x += acc[mi][ni][2]; v1.y += acc[mi][ni][3];
                *p0 = v0; *p1 = v1;
            } else {
                *p0 = make_float2(acc[mi][ni][0], acc[mi][ni][1]);
                *p1 = make_float2(acc[mi][ni][2], acc[mi][ni][3]);
            }
        }
    }
}

constexpr int SMEM_BN256 = 1024 + 3 * (8192 + 256 * 64);   // 74752
constexpr int SMEM_BN128 = 1024 + 3 * (8192 + 128 * 64);   // 50176

// ---------------------------------------------------------------------------
// Causal depthwise conv (K=4) + bias + silu
// ---------------------------------------------------------------------------
__global__ void conv_silu_kernel(const float* __restrict__ cw,
                                 const float* __restrict__ cb) {
    int i = blockIdx.x * blockDim.x + threadIdx.x;
    int t = i / kDi, c = i - t * kDi;
    float w0 = cw[c * 4 + 0], w1 = cw[c * 4 + 1];
    float w2 = cw[c * 4 + 2], w3 = cw[c * 4 + 3];
    const int stride = 2 * kDi;
    float s = cb[c];
    if (t >= 3) s += w0 * g_xz[(size_t)(t - 3) * stride + c];
    if (t >= 2) s += w1 * g_xz[(size_t)(t - 2) * stride + c];
    if (t >= 1) s += w2 * g_xz[(size_t)(t - 1) * stride + c];
    s += w3 * g_xz[(size_t)t * stride + c];
    g_u[i] = s / (1.f + __expf(-s));
}

// ---------------------------------------------------------------------------
// x_proj
// ---------------------------------------------------------------------------
__global__ void xproj_kernel(const float* __restrict__ W) {
    int t = blockIdx.x;
    int warp = threadIdx.x >> 5, lane = threadIdx.x & 31;
    const float4* ur = (const float4*)(g_u + (size_t)t * kDi);
    for (int j = warp; j < kXP; j += 8) {
        const float4* wr = (const float4*)(W + (size_t)j * kDi);
        float s = 0.f;
        #pragma unroll 4
        for (int k = lane; k < kDi / 4; k += 32) {
            float4 a = ur[k], b = wr[k];
            s += a.x * b.x + a.y * b.y + a.z * b.z + a.w * b.w;
        }
        #pragma unroll
        for (int o = 16; o; o >>= 1) s += __shfl_xor_sync(0xffffffffu, s, o);
        if (lane == 0) g_xp[t * kXP + j] = s;
    }
}

// ---------------------------------------------------------------------------
// Selective scan -> packed swizzled fp16 (tile rows 128, K=kDi)
// ---------------------------------------------------------------------------
__global__ void scan_kernel(const float* __restrict__ A_log,
                            const float* __restrict__ dtw_,
                            const float* __restrict__ dtb_,
                            const float* __restrict__ Dp_) {
    int tid = threadIdx.x;
    int n = tid & 15;
    int g = tid >> 4;
    int d = blockIdx.x * 8 + g;
    float a   = -expf(A_log[(size_t)d * kNS + n]);
    float dtw = dtw_[d];
    float dtb = dtb_[d];
    float Dp  = Dp_[d];
    const int NKt = kDi >> 5;   // 64
    int kb = d >> 5, col = d & 31;
    float h = 0.f;
    for (int t = 0; t < kT; t++) {
        const float* xpr = g_xp + (size_t)t * kXP;
        float dtr = xpr[0];
        float xv = dtr * dtw + dtb;
        float dt = (xv > 20.f) ? xv : log1pf(__expf(xv));
        float Bn = xpr[1 + n];
        float Cn = xpr[17 + n];
        float ut = g_u[(size_t)t * kDi + d];
        float dA = __expf(dt * a);
        h = dA * h + (dt * ut) * Bn;
        float p = h * Cn;
        p += __shfl_xor_sync(0xffffffffu, p, 8);
        p += __shfl_xor_sync(0xffffffffu, p, 4);
        p += __shfl_xor_sync(0xffffffffu, p, 2);
        p += __shfl_xor_sync(0xffffffffu, p, 1);
        if (n == 0) {
            float z = g_xz[(size_t)t * (2 * kDi) + kDi + d];
            float y = p + ut * Dp;
            int tb = t >> 7, r = t & 127;
            size_t off = ((size_t)(tb * NKt + kb) * 8192) +
                         (uint32_t)((r * 64 + col * 2) ^ ((r & 7) << 3));
            *(__half*)((char*)g_ygh + off) =
                __float2half_rn(y * (z / (1.f + __expf(-z))));
        }
    }
}

// ---------------------------------------------------------------------------
// Host launcher
// ---------------------------------------------------------------------------
extern "C" void kernel_launch(void* const* d_in, const int* in_sizes, int n_in,
                              void* d_out, int out_size) {
    const int*   idx        = (const int*)  d_in[0];
    const float* emb        = (const float*)d_in[1];
    const float* norm_w     = (const float*)d_in[2];
    const float* in_proj_w  = (const float*)d_in[3];
    const float* conv_w     = (const float*)d_in[4];
    const float* conv_b     = (const float*)d_in[5];
    const float* x_proj_w   = (const float*)d_in[6];
    const float* dt_proj_w  = (const float*)d_in[7];
    const float* dt_proj_b  = (const float*)d_in[8];
    const float* A_log      = (const float*)d_in[9];
    const float* D_param    = (const float*)d_in[10];
    const float* out_proj_w = (const float*)d_in[11];
    const float* norm_f_w   = (const float*)d_in[12];
    float* out = (float*)d_out;

    float *x, *xz;
    __half *xnh, *ygh, *wh_in, *wh_out, *embh;
    cudaGetSymbolAddress((void**)&x,      g_x);
    cudaGetSymbolAddress((void**)&xnh,    g_xnh);
    cudaGetSymbolAddress((void**)&xz,     g_xz);
    cudaGetSymbolAddress((void**)&ygh,    g_ygh);
    cudaGetSymbolAddress((void**)&wh_in,  g_wh_in);
    cudaGetSymbolAddress((void**)&wh_out, g_wh_out);
    cudaGetSymbolAddress((void**)&embh,   g_embh);

    cudaFuncSetAttribute(gemm_bulk<256, 512>,
                         cudaFuncAttributeMaxDynamicSharedMemorySize, SMEM_BN256);
    cudaFuncSetAttribute(gemm_bulk<128, 256>,
                         cudaFuncAttributeMaxDynamicSharedMemorySize, SMEM_BN128);

    // Convert + pack weights (every launch; deterministic)
    {
        long n1 = (long)kNL * 2 * kDi * kDm / 4;
        long n2 = (long)kNL * kDm * kDi / 4;
        long n3 = (long)kV * kDm / 4;
        pack_w_kernel<256><<<(int)((n1 + 255) / 256), 256>>>(in_proj_w,  wh_in,
                                                             kNL * 2 * kDi, kDm);
        pack_w_kernel<128><<<(int)((n2 + 255) / 256), 256>>>(out_proj_w, wh_out,
                                                             kNL * kDm, kDi);
        pack_w_kernel<256><<<(int)((n3 + 255) / 256), 256>>>(emb,        embh,
                                                             kV, kDm);
    }

    embed_kernel<<<kT, 256>>>(idx, emb);

    for (int l = 0; l < kNL; l++) {
        rmsnorm_kernel<<<kT, 256>>>(x, norm_w + (size_t)l * kDm, xnh);
        gemm_bulk<256, 512><<<dim3(2 * kDi / 256, kT / 128), 512, SMEM_BN256>>>(
            xnh, wh_in + (size_t)l * 2 * kDi * kDm, xz, kT, 2 * kDi, kDm, 0);
        conv_silu_kernel<<<kT * kDi / 256, 256>>>(
            conv_w + (size_t)l * kDi * 4, conv_b + (size_t)l * kDi);
        xproj_kernel<<<kT, 256>>>(x_proj_w + (size_t)l * kXP * kDi);
        scan_kernel<<<kDi / 8, 128>>>(
            A_log + (size_t)l * kDi * kNS,
            dt_proj_w + (size_t)l * kDi,
            dt_proj_b + (size_t)l * kDi,
            D_param + (size_t)l * kDi);
        gemm_bulk<128, 256><<<dim3(kDm / 128, kT / 128), 256, SMEM_BN128>>>(
            ygh, wh_out + (size_t)l * kDm * kDi, x, kT, kDm, kDi, 1);
    }

    rmsnorm_kernel<<<kT, 256>>>(x, norm_f_w, xnh);
    gemm_bulk<256, 512><<<dim3(kV / 256, kT / 128), 512, SMEM_BN256>>>(
        xnh, embh, out, kT, kV, kDm, 0);
}